// round 9
// baseline (speedup 1.0000x reference)
#include <cuda_runtime.h>
#include <cuda_fp16.h>

#define N_NODES 100000
#define N_PAD   100032   // multiple of 64
#define N_EDGES 3200000
#define F0 64
#define F1 128
#define F2 64
#define N_CHUNKS 98   // ceil(100000/1024)

// Scratch (static __device__ arrays)
__device__ int   g_degi[N_NODES];
__device__ int   g_scan[N_NODES];
__device__ int   g_chunksum[N_CHUNKS];
__device__ int   g_chunkoff[N_CHUNKS];
__device__ int   g_row [N_NODES + 1];
__device__ int   g_cur [N_NODES];
__device__ int   g_csr [N_EDGES];
__device__ float g_dinv[N_PAD];
__device__ unsigned g_xh [N_NODES * 32];  // fp16: x * dinv[node], 2 halves per unsigned
__device__ float g_ag  [N_PAD * F0];      // fp32 aggregated input-space features
__device__ float g_h2  [N_PAD * F1];      // fp32 relu'd layer-1 output
__device__ unsigned g_h2h[N_PAD * 32];    // fp16: (h2 @ W2) * dinv

// ---------------------------------------------------------------------------
__global__ void k_deg_count(const int* __restrict__ dst) {
    int e = blockIdx.x * blockDim.x + threadIdx.x;
    if (e < N_EDGES) atomicAdd(&g_degi[dst[e]], 1);
}

__device__ __forceinline__ unsigned pack2(float lo, float hi) {
    __half2 h = __floats2half2_rn(lo, hi);
    return *(unsigned*)&h;
}

// Scan chunk + dinv + fused prescale of this chunk's x rows.
__global__ void k_scan_chunk(const float* __restrict__ x) {
    __shared__ int sh[1024];
    __shared__ float sdinv[1024];
    int gid = blockIdx.x * 1024 + threadIdx.x;
    int v = (gid < N_NODES) ? g_degi[gid] : 0;
    float di = rsqrtf((float)(v + 1));       // self-loop included
    if (gid < N_PAD) g_dinv[gid] = di;
    sdinv[threadIdx.x] = di;
    sh[threadIdx.x] = v;
    __syncthreads();
    #pragma unroll
    for (int off = 1; off < 1024; off <<= 1) {
        int t = (threadIdx.x >= off) ? sh[threadIdx.x - off] : 0;
        __syncthreads();
        sh[threadIdx.x] += t;
        __syncthreads();
    }
    if (gid < N_NODES) g_scan[gid] = sh[threadIdx.x];     // inclusive
    if (threadIdx.x == 1023) g_chunksum[blockIdx.x] = sh[1023];

    // Fused prescale: pack x rows of this chunk to fp16 (one float4 -> one unsigned2... 
    // here: one float2 -> one unsigned per element step of 2 floats).
    // Process 1024 nodes x 32 unsigned = 32768 elems; each elem = 2 floats of x.
    int base = blockIdx.x * 1024 * 32;      // unsigned index
    for (int t = threadIdx.x; t < 1024 * 32; t += 1024) {
        int idx = base + t;
        if (idx < N_NODES * 32) {
            float dd = sdinv[t >> 5];
            float2 a = *(const float2*)&x[(size_t)idx * 2];
            g_xh[idx] = pack2(a.x * dd, a.y * dd);
        }
    }
}

__global__ void k_scan_sums() {    // 1 block, 128 threads
    __shared__ int sh[128];
    int tid = threadIdx.x;
    int v = (tid < N_CHUNKS) ? g_chunksum[tid] : 0;
    sh[tid] = v;
    __syncthreads();
    #pragma unroll
    for (int off = 1; off < 128; off <<= 1) {
        int t = (tid >= off) ? sh[tid - off] : 0;
        __syncthreads();
        sh[tid] += t;
        __syncthreads();
    }
    if (tid < N_CHUNKS) g_chunkoff[tid] = sh[tid] - v;    // exclusive
}

__global__ void k_row_ptr() {
    int i = blockIdx.x * blockDim.x + threadIdx.x;
    if (i < N_NODES) {
        int r = g_scan[i] - g_degi[i] + g_chunkoff[i >> 10];
        g_row[i] = r;
        g_cur[i] = r;
    }
    if (i == 0) g_row[N_NODES] = N_EDGES;
}

__global__ void k_csr_fill(const int* __restrict__ src, const int* __restrict__ dst) {
    int e = blockIdx.x * blockDim.x + threadIdx.x;
    if (e < N_EDGES) {
        int pos = atomicAdd(&g_cur[dst[e]], 1);
        g_csr[pos] = src[e];
    }
}

// ---------------------------------------------------------------------------
// Pull (64-dim fp16 storage, fp32 accum): FULL warp per node, 2 features/lane.
// Uniform control flow within the warp; MLP-8 gathers.
// ---------------------------------------------------------------------------
__device__ __forceinline__ void acc_u(float2& acc, unsigned u) {
    float2 f = __half22float2(*(__half2*)&u);
    acc.x += f.x; acc.y += f.y;
}

__device__ __forceinline__ float2 pull64w(const unsigned* __restrict__ feat,
                                          int node, int lane) {
    int beg = g_row[node], end = g_row[node + 1];
    float2 acc = make_float2(0.f, 0.f);
    acc_u(acc, feat[(size_t)node * 32 + lane]);        // self-loop
    for (int e0 = beg; e0 < end; e0 += 32) {
        int n = end - e0;
        int s = (lane < n) ? g_csr[e0 + lane] : 0;
        int cnt = min(n, 32);
        int i = 0;
        for (; i + 8 <= cnt; i += 8) {
            unsigned u[8];
            #pragma unroll
            for (int j = 0; j < 8; ++j) {
                int ss = __shfl_sync(0xffffffffu, s, i + j);
                u[j] = feat[(size_t)ss * 32 + lane];
            }
            #pragma unroll
            for (int j = 0; j < 8; ++j) acc_u(acc, u[j]);
        }
        for (; i + 4 <= cnt; i += 4) {
            unsigned u[4];
            #pragma unroll
            for (int j = 0; j < 4; ++j) {
                int ss = __shfl_sync(0xffffffffu, s, i + j);
                u[j] = feat[(size_t)ss * 32 + lane];
            }
            #pragma unroll
            for (int j = 0; j < 4; ++j) acc_u(acc, u[j]);
        }
        for (; i < cnt; ++i) {
            int ss = __shfl_sync(0xffffffffu, s, i);
            acc_u(acc, feat[(size_t)ss * 32 + lane]);
        }
    }
    return acc;
}

__global__ void k_pull1() {
    int lane = threadIdx.x & 31;
    int node = (blockIdx.x * blockDim.x + threadIdx.x) >> 5;
    if (node >= N_NODES) return;
    float2 acc = pull64w(g_xh, node, lane);
    float di = g_dinv[node];
    acc.x *= di; acc.y *= di;
    *(float2*)&g_ag[(size_t)node * F0 + lane * 2] = acc;
}

__global__ void k_pull2(const float* __restrict__ b2, float* __restrict__ out) {
    int lane = threadIdx.x & 31;
    int node = (blockIdx.x * blockDim.x + threadIdx.x) >> 5;
    if (node >= N_NODES) return;
    float2 acc = pull64w(g_h2h, node, lane);
    float di = g_dinv[node];
    float2 bb = *(const float2*)&b2[lane * 2];
    float2 o;
    o.x = fmaf(acc.x, di, bb.x);
    o.y = fmaf(acc.y, di, bb.y);
    *(float2*)&out[(size_t)node * F2 + lane * 2] = o;
}

// ---------------------------------------------------------------------------
// tf32 helpers
// ---------------------------------------------------------------------------
__device__ __forceinline__ float tf32r(float f) {
    unsigned u;
    asm("cvt.rna.tf32.f32 %0, %1;" : "=r"(u) : "f"(f));
    return __uint_as_float(u);
}

__device__ __forceinline__ void mma_tf32(float c[4], unsigned a0, unsigned a1,
                                         unsigned a2, unsigned a3,
                                         unsigned b0, unsigned b1) {
    asm volatile(
        "mma.sync.aligned.m16n8k8.row.col.f32.tf32.tf32.f32 "
        "{%0,%1,%2,%3}, {%4,%5,%6,%7}, {%8,%9}, {%0,%1,%2,%3};"
        : "+f"(c[0]), "+f"(c[1]), "+f"(c[2]), "+f"(c[3])
        : "r"(a0), "r"(a1), "r"(a2), "r"(a3), "r"(b0), "r"(b1));
}

// ---------------------------------------------------------------------------
// GEMM1 (tensor): h2 = relu(ag @ W1 + b1).  Tile 64x128, K=64, 256 threads.
// ---------------------------------------------------------------------------
#define G1_SMEM ((128 * 68 + 64 * 68) * 4)
__global__ void k_gemm1(const float* __restrict__ W1, const float* __restrict__ b1) {
    extern __shared__ float sm[];
    float* Wt = sm;              // [128][68]
    float* As = sm + 128 * 68;   // [64][68]
    int tid = threadIdx.x;       // 256

    for (int i = tid; i < F0 * F1; i += 256) {
        int k = i >> 7, n = i & 127;
        Wt[n * 68 + k] = tf32r(W1[i]);
    }
    int r0 = blockIdx.x * 64;
    #pragma unroll
    for (int t = 0; t < 4; ++t) {
        int f4 = tid + t * 256;
        int r = f4 >> 4, c = (f4 & 15) * 4;
        float4 v = *(const float4*)&g_ag[(size_t)(r0 + r) * F0 + c];
        As[r * 68 + c + 0] = tf32r(v.x);
        As[r * 68 + c + 1] = tf32r(v.y);
        As[r * 68 + c + 2] = tf32r(v.z);
        As[r * 68 + c + 3] = tf32r(v.w);
    }
    __syncthreads();

    int lane = tid & 31, warp = tid >> 5;
    int wr = (warp & 3) * 16;
    int wc = (warp >> 2) * 64;
    int g = lane >> 2, tg = lane & 3;

    float c[8][4];
    #pragma unroll
    for (int nt = 0; nt < 8; ++nt)
        c[nt][0] = c[nt][1] = c[nt][2] = c[nt][3] = 0.f;

    #pragma unroll
    for (int ks = 0; ks < 8; ++ks) {
        int k0 = ks * 8 + tg;
        unsigned a0 = __float_as_uint(As[(wr + g    ) * 68 + k0]);
        unsigned a1 = __float_as_uint(As[(wr + g + 8) * 68 + k0]);
        unsigned a2 = __float_as_uint(As[(wr + g    ) * 68 + k0 + 4]);
        unsigned a3 = __float_as_uint(As[(wr + g + 8) * 68 + k0 + 4]);
        #pragma unroll
        for (int nt = 0; nt < 8; ++nt) {
            const float* bp = &Wt[(wc + nt * 8 + g) * 68 + k0];
            mma_tf32(c[nt], a0, a1, a2, a3,
                     __float_as_uint(bp[0]), __float_as_uint(bp[4]));
        }
    }

    #pragma unroll
    for (int nt = 0; nt < 8; ++nt) {
        int col = wc + nt * 8 + tg * 2;
        float2 bb = *(const float2*)&b1[col];
        int row = r0 + wr + g;
        float2 o0 = { fmaxf(c[nt][0] + bb.x, 0.f), fmaxf(c[nt][1] + bb.y, 0.f) };
        *(float2*)&g_h2[(size_t)row * F1 + col] = o0;
        float2 o1 = { fmaxf(c[nt][2] + bb.x, 0.f), fmaxf(c[nt][3] + bb.y, 0.f) };
        *(float2*)&g_h2[(size_t)(row + 8) * F1 + col] = o1;
    }
}

// ---------------------------------------------------------------------------
// GEMM2 (tensor): h2h = half((h2 @ W2) * dinv).  Tile 64x64, K=128.
// ---------------------------------------------------------------------------
#define G2_SMEM ((64 * 132 + 64 * 132) * 4)
__global__ void k_gemm2(const float* __restrict__ W2) {
    extern __shared__ float sm[];
    float* Wt = sm;              // [64][132]
    float* As = sm + 64 * 132;   // [64][132]
    int tid = threadIdx.x;       // 256

    for (int i = tid; i < F1 * F2; i += 256) {
        int k = i >> 6, n = i & 63;
        Wt[n * 132 + k] = tf32r(W2[i]);
    }
    int r0 = blockIdx.x * 64;
    #pragma unroll
    for (int t = 0; t < 8; ++t) {
        int f4 = tid + t * 256;
        int r = f4 >> 5, c = (f4 & 31) * 4;
        float4 v = *(const float4*)&g_h2[(size_t)(r0 + r) * F1 + c];
        As[r * 132 + c + 0] = tf32r(v.x);
        As[r * 132 + c + 1] = tf32r(v.y);
        As[r * 132 + c + 2] = tf32r(v.z);
        As[r * 132 + c + 3] = tf32r(v.w);
    }
    __syncthreads();

    int lane = tid & 31, warp = tid >> 5;
    int wr = (warp & 3) * 16;
    int wc = (warp >> 2) * 32;
    int g = lane >> 2, tg = lane & 3;

    float c[4][4];
    #pragma unroll
    for (int nt = 0; nt < 4; ++nt)
        c[nt][0] = c[nt][1] = c[nt][2] = c[nt][3] = 0.f;

    #pragma unroll
    for (int ks = 0; ks < 16; ++ks) {
        int k0 = ks * 8 + tg;
        unsigned a0 = __float_as_uint(As[(wr + g    ) * 132 + k0]);
        unsigned a1 = __float_as_uint(As[(wr + g + 8) * 132 + k0]);
        unsigned a2 = __float_as_uint(As[(wr + g    ) * 132 + k0 + 4]);
        unsigned a3 = __float_as_uint(As[(wr + g + 8) * 132 + k0 + 4]);
        #pragma unroll
        for (int nt = 0; nt < 4; ++nt) {
            const float* bp = &Wt[(wc + nt * 8 + g) * 132 + k0];
            mma_tf32(c[nt], a0, a1, a2, a3,
                     __float_as_uint(bp[0]), __float_as_uint(bp[4]));
        }
    }

    #pragma unroll
    for (int nt = 0; nt < 4; ++nt) {
        int col = wc + nt * 8 + tg * 2;
        int row = r0 + wr + g;
        float d0 = g_dinv[row];
        g_h2h[(size_t)row * 32 + (col >> 1)] = pack2(c[nt][0] * d0, c[nt][1] * d0);
        float d1 = g_dinv[row + 8];
        g_h2h[(size_t)(row + 8) * 32 + (col >> 1)] = pack2(c[nt][2] * d1, c[nt][3] * d1);
    }
}

// ---------------------------------------------------------------------------
extern "C" void kernel_launch(void* const* d_in, const int* in_sizes, int n_in,
                              void* d_out, int out_size) {
    const float* x   = (const float*)d_in[0];
    const int*   ei  = (const int*)d_in[1];   // [2, E] int32
    const float* W1  = (const float*)d_in[2];
    const float* b1  = (const float*)d_in[3];
    const float* W2  = (const float*)d_in[4];
    const float* b2  = (const float*)d_in[5];
    float*       out = (float*)d_out;

    const int* src = ei;
    const int* dst = ei + N_EDGES;

    cudaFuncSetAttribute(k_gemm1, cudaFuncAttributeMaxDynamicSharedMemorySize, G1_SMEM);
    cudaFuncSetAttribute(k_gemm2, cudaFuncAttributeMaxDynamicSharedMemorySize, G2_SMEM);

    // degree zero via memset node
    void* degi_ptr = nullptr;
    cudaGetSymbolAddress(&degi_ptr, g_degi);
    cudaMemsetAsync(degi_ptr, 0, N_NODES * sizeof(int));

    // degree + dinv + CSR (+ fused prescale in scan_chunk)
    k_deg_count<<<(N_EDGES + 255) / 256, 256>>>(dst);
    k_scan_chunk<<<N_CHUNKS, 1024>>>(x);              // dinv + prescale fused
    k_scan_sums<<<1, 128>>>();
    k_row_ptr  <<<(N_NODES + 255) / 256, 256>>>();
    k_csr_fill <<<(N_EDGES + 255) / 256, 256>>>(src, dst);

    // layer 1: pull(64-dim fp16, warp/node) -> tensor gemm(+bias+relu)
    k_pull1<<<(N_NODES * 32 + 255) / 256, 256>>>();
    k_gemm1<<<N_PAD / 64, 256, G1_SMEM>>>(W1, b1);

    // layer 2: tensor gemm(*dinv -> fp16) -> pull(64-dim fp16, +bias)
    k_gemm2<<<N_PAD / 64, 256, G2_SMEM>>>(W2);
    k_pull2<<<(N_NODES * 32 + 255) / 256, 256>>>(b2, out);
}

// round 10
// speedup vs baseline: 1.0060x; 1.0060x over previous
#include <cuda_runtime.h>
#include <cuda_fp16.h>

#define N_NODES 100000
#define N_PAD   100032   // multiple of 64
#define N_EDGES 3200000
#define F0 64
#define F1 128
#define F2 64
#define N_CHUNKS 98   // ceil(100000/1024)

// Scratch (static __device__ arrays)
__device__ int   g_degi[N_NODES];
__device__ int   g_scan[N_NODES];
__device__ int   g_chunksum[N_CHUNKS];
__device__ int   g_chunkoff[N_CHUNKS];
__device__ int   g_row [N_NODES + 1];
__device__ int   g_cur [N_NODES];
__device__ int   g_csr [N_EDGES];
__device__ float g_dinv[N_PAD];
__device__ unsigned g_xh [N_NODES * 32];  // fp16: x * dinv[node], 2 halves per unsigned
__device__ float g_ag  [N_PAD * F0];      // fp32 aggregated input-space features
__device__ float g_h2  [N_PAD * F1];      // fp32 relu'd layer-1 output
__device__ unsigned g_h2h[N_PAD * 32];    // fp16: (h2 @ W2) * dinv

// ---------------------------------------------------------------------------
__global__ void k_deg_count(const int* __restrict__ dst) {
    int e = blockIdx.x * blockDim.x + threadIdx.x;
    if (e < N_EDGES) atomicAdd(&g_degi[dst[e]], 1);
}

__device__ __forceinline__ unsigned pack2(float lo, float hi) {
    __half2 h = __floats2half2_rn(lo, hi);
    return *(unsigned*)&h;
}

// Scan chunk + dinv + fused prescale of this chunk's x rows.
__global__ void k_scan_chunk(const float* __restrict__ x) {
    __shared__ int sh[1024];
    __shared__ float sdinv[1024];
    int gid = blockIdx.x * 1024 + threadIdx.x;
    int v = (gid < N_NODES) ? g_degi[gid] : 0;
    float di = rsqrtf((float)(v + 1));       // self-loop included
    if (gid < N_PAD) g_dinv[gid] = di;
    sdinv[threadIdx.x] = di;
    sh[threadIdx.x] = v;
    __syncthreads();
    #pragma unroll
    for (int off = 1; off < 1024; off <<= 1) {
        int t = (threadIdx.x >= off) ? sh[threadIdx.x - off] : 0;
        __syncthreads();
        sh[threadIdx.x] += t;
        __syncthreads();
    }
    if (gid < N_NODES) g_scan[gid] = sh[threadIdx.x];     // inclusive
    if (threadIdx.x == 1023) g_chunksum[blockIdx.x] = sh[1023];

    // Fused prescale: pack x rows of this chunk to fp16 (one float4 -> one unsigned2... 
    // here: one float2 -> one unsigned per element step of 2 floats).
    // Process 1024 nodes x 32 unsigned = 32768 elems; each elem = 2 floats of x.
    int base = blockIdx.x * 1024 * 32;      // unsigned index
    for (int t = threadIdx.x; t < 1024 * 32; t += 1024) {
        int idx = base + t;
        if (idx < N_NODES * 32) {
            float dd = sdinv[t >> 5];
            float2 a = *(const float2*)&x[(size_t)idx * 2];
            g_xh[idx] = pack2(a.x * dd, a.y * dd);
        }
    }
}

__global__ void k_scan_sums() {    // 1 block, 128 threads
    __shared__ int sh[128];
    int tid = threadIdx.x;
    int v = (tid < N_CHUNKS) ? g_chunksum[tid] : 0;
    sh[tid] = v;
    __syncthreads();
    #pragma unroll
    for (int off = 1; off < 128; off <<= 1) {
        int t = (tid >= off) ? sh[tid - off] : 0;
        __syncthreads();
        sh[tid] += t;
        __syncthreads();
    }
    if (tid < N_CHUNKS) g_chunkoff[tid] = sh[tid] - v;    // exclusive
}

__global__ void k_row_ptr() {
    int i = blockIdx.x * blockDim.x + threadIdx.x;
    if (i < N_NODES) {
        int r = g_scan[i] - g_degi[i] + g_chunkoff[i >> 10];
        g_row[i] = r;
        g_cur[i] = r;
    }
    if (i == 0) g_row[N_NODES] = N_EDGES;
}

__global__ void k_csr_fill(const int* __restrict__ src, const int* __restrict__ dst) {
    int e = blockIdx.x * blockDim.x + threadIdx.x;
    if (e < N_EDGES) {
        int pos = atomicAdd(&g_cur[dst[e]], 1);
        g_csr[pos] = src[e];
    }
}

// ---------------------------------------------------------------------------
// Pull (64-dim fp16 storage, fp32 accum): FULL warp per node, 2 features/lane.
// Uniform control flow within the warp; MLP-8 gathers.
// ---------------------------------------------------------------------------
__device__ __forceinline__ void acc_u(float2& acc, unsigned u) {
    float2 f = __half22float2(*(__half2*)&u);
    acc.x += f.x; acc.y += f.y;
}

__device__ __forceinline__ float2 pull64w(const unsigned* __restrict__ feat,
                                          int node, int lane) {
    int beg = g_row[node], end = g_row[node + 1];
    float2 acc = make_float2(0.f, 0.f);
    acc_u(acc, feat[(size_t)node * 32 + lane]);        // self-loop
    for (int e0 = beg; e0 < end; e0 += 32) {
        int n = end - e0;
        int s = (lane < n) ? g_csr[e0 + lane] : 0;
        int cnt = min(n, 32);
        int i = 0;
        for (; i + 8 <= cnt; i += 8) {
            unsigned u[8];
            #pragma unroll
            for (int j = 0; j < 8; ++j) {
                int ss = __shfl_sync(0xffffffffu, s, i + j);
                u[j] = feat[(size_t)ss * 32 + lane];
            }
            #pragma unroll
            for (int j = 0; j < 8; ++j) acc_u(acc, u[j]);
        }
        for (; i + 4 <= cnt; i += 4) {
            unsigned u[4];
            #pragma unroll
            for (int j = 0; j < 4; ++j) {
                int ss = __shfl_sync(0xffffffffu, s, i + j);
                u[j] = feat[(size_t)ss * 32 + lane];
            }
            #pragma unroll
            for (int j = 0; j < 4; ++j) acc_u(acc, u[j]);
        }
        for (; i < cnt; ++i) {
            int ss = __shfl_sync(0xffffffffu, s, i);
            acc_u(acc, feat[(size_t)ss * 32 + lane]);
        }
    }
    return acc;
}

__global__ void k_pull1() {
    int lane = threadIdx.x & 31;
    int node = (blockIdx.x * blockDim.x + threadIdx.x) >> 5;
    if (node >= N_NODES) return;
    float2 acc = pull64w(g_xh, node, lane);
    float di = g_dinv[node];
    acc.x *= di; acc.y *= di;
    *(float2*)&g_ag[(size_t)node * F0 + lane * 2] = acc;
}

__global__ void k_pull2(const float* __restrict__ b2, float* __restrict__ out) {
    int lane = threadIdx.x & 31;
    int node = (blockIdx.x * blockDim.x + threadIdx.x) >> 5;
    if (node >= N_NODES) return;
    float2 acc = pull64w(g_h2h, node, lane);
    float di = g_dinv[node];
    float2 bb = *(const float2*)&b2[lane * 2];
    float2 o;
    o.x = fmaf(acc.x, di, bb.x);
    o.y = fmaf(acc.y, di, bb.y);
    *(float2*)&out[(size_t)node * F2 + lane * 2] = o;
}

// ---------------------------------------------------------------------------
// tf32 helpers
// ---------------------------------------------------------------------------
__device__ __forceinline__ float tf32r(float f) {
    unsigned u;
    asm("cvt.rna.tf32.f32 %0, %1;" : "=r"(u) : "f"(f));
    return __uint_as_float(u);
}

__device__ __forceinline__ void mma_tf32(float c[4], unsigned a0, unsigned a1,
                                         unsigned a2, unsigned a3,
                                         unsigned b0, unsigned b1) {
    asm volatile(
        "mma.sync.aligned.m16n8k8.row.col.f32.tf32.tf32.f32 "
        "{%0,%1,%2,%3}, {%4,%5,%6,%7}, {%8,%9}, {%0,%1,%2,%3};"
        : "+f"(c[0]), "+f"(c[1]), "+f"(c[2]), "+f"(c[3])
        : "r"(a0), "r"(a1), "r"(a2), "r"(a3), "r"(b0), "r"(b1));
}

// ---------------------------------------------------------------------------
// GEMM1 (tensor): h2 = relu(ag @ W1 + b1).  Tile 64x128, K=64, 256 threads.
// ---------------------------------------------------------------------------
#define G1_SMEM ((128 * 68 + 64 * 68) * 4)
__global__ void k_gemm1(const float* __restrict__ W1, const float* __restrict__ b1) {
    extern __shared__ float sm[];
    float* Wt = sm;              // [128][68]
    float* As = sm + 128 * 68;   // [64][68]
    int tid = threadIdx.x;       // 256

    for (int i = tid; i < F0 * F1; i += 256) {
        int k = i >> 7, n = i & 127;
        Wt[n * 68 + k] = tf32r(W1[i]);
    }
    int r0 = blockIdx.x * 64;
    #pragma unroll
    for (int t = 0; t < 4; ++t) {
        int f4 = tid + t * 256;
        int r = f4 >> 4, c = (f4 & 15) * 4;
        float4 v = *(const float4*)&g_ag[(size_t)(r0 + r) * F0 + c];
        As[r * 68 + c + 0] = tf32r(v.x);
        As[r * 68 + c + 1] = tf32r(v.y);
        As[r * 68 + c + 2] = tf32r(v.z);
        As[r * 68 + c + 3] = tf32r(v.w);
    }
    __syncthreads();

    int lane = tid & 31, warp = tid >> 5;
    int wr = (warp & 3) * 16;
    int wc = (warp >> 2) * 64;
    int g = lane >> 2, tg = lane & 3;

    float c[8][4];
    #pragma unroll
    for (int nt = 0; nt < 8; ++nt)
        c[nt][0] = c[nt][1] = c[nt][2] = c[nt][3] = 0.f;

    #pragma unroll
    for (int ks = 0; ks < 8; ++ks) {
        int k0 = ks * 8 + tg;
        unsigned a0 = __float_as_uint(As[(wr + g    ) * 68 + k0]);
        unsigned a1 = __float_as_uint(As[(wr + g + 8) * 68 + k0]);
        unsigned a2 = __float_as_uint(As[(wr + g    ) * 68 + k0 + 4]);
        unsigned a3 = __float_as_uint(As[(wr + g + 8) * 68 + k0 + 4]);
        #pragma unroll
        for (int nt = 0; nt < 8; ++nt) {
            const float* bp = &Wt[(wc + nt * 8 + g) * 68 + k0];
            mma_tf32(c[nt], a0, a1, a2, a3,
                     __float_as_uint(bp[0]), __float_as_uint(bp[4]));
        }
    }

    #pragma unroll
    for (int nt = 0; nt < 8; ++nt) {
        int col = wc + nt * 8 + tg * 2;
        float2 bb = *(const float2*)&b1[col];
        int row = r0 + wr + g;
        float2 o0 = { fmaxf(c[nt][0] + bb.x, 0.f), fmaxf(c[nt][1] + bb.y, 0.f) };
        *(float2*)&g_h2[(size_t)row * F1 + col] = o0;
        float2 o1 = { fmaxf(c[nt][2] + bb.x, 0.f), fmaxf(c[nt][3] + bb.y, 0.f) };
        *(float2*)&g_h2[(size_t)(row + 8) * F1 + col] = o1;
    }
}

// ---------------------------------------------------------------------------
// GEMM2 (tensor): h2h = half((h2 @ W2) * dinv).  Tile 64x64, K=128.
// ---------------------------------------------------------------------------
#define G2_SMEM ((64 * 132 + 64 * 132) * 4)
__global__ void k_gemm2(const float* __restrict__ W2) {
    extern __shared__ float sm[];
    float* Wt = sm;              // [64][132]
    float* As = sm + 64 * 132;   // [64][132]
    int tid = threadIdx.x;       // 256

    for (int i = tid; i < F1 * F2; i += 256) {
        int k = i >> 6, n = i & 63;
        Wt[n * 132 + k] = tf32r(W2[i]);
    }
    int r0 = blockIdx.x * 64;
    #pragma unroll
    for (int t = 0; t < 8; ++t) {
        int f4 = tid + t * 256;
        int r = f4 >> 5, c = (f4 & 31) * 4;
        float4 v = *(const float4*)&g_h2[(size_t)(r0 + r) * F1 + c];
        As[r * 132 + c + 0] = tf32r(v.x);
        As[r * 132 + c + 1] = tf32r(v.y);
        As[r * 132 + c + 2] = tf32r(v.z);
        As[r * 132 + c + 3] = tf32r(v.w);
    }
    __syncthreads();

    int lane = tid & 31, warp = tid >> 5;
    int wr = (warp & 3) * 16;
    int wc = (warp >> 2) * 32;
    int g = lane >> 2, tg = lane & 3;

    float c[4][4];
    #pragma unroll
    for (int nt = 0; nt < 4; ++nt)
        c[nt][0] = c[nt][1] = c[nt][2] = c[nt][3] = 0.f;

    #pragma unroll
    for (int ks = 0; ks < 16; ++ks) {
        int k0 = ks * 8 + tg;
        unsigned a0 = __float_as_uint(As[(wr + g    ) * 132 + k0]);
        unsigned a1 = __float_as_uint(As[(wr + g + 8) * 132 + k0]);
        unsigned a2 = __float_as_uint(As[(wr + g    ) * 132 + k0 + 4]);
        unsigned a3 = __float_as_uint(As[(wr + g + 8) * 132 + k0 + 4]);
        #pragma unroll
        for (int nt = 0; nt < 4; ++nt) {
            const float* bp = &Wt[(wc + nt * 8 + g) * 132 + k0];
            mma_tf32(c[nt], a0, a1, a2, a3,
                     __float_as_uint(bp[0]), __float_as_uint(bp[4]));
        }
    }

    #pragma unroll
    for (int nt = 0; nt < 4; ++nt) {
        int col = wc + nt * 8 + tg * 2;
        int row = r0 + wr + g;
        float d0 = g_dinv[row];
        g_h2h[(size_t)row * 32 + (col >> 1)] = pack2(c[nt][0] * d0, c[nt][1] * d0);
        float d1 = g_dinv[row + 8];
        g_h2h[(size_t)(row + 8) * 32 + (col >> 1)] = pack2(c[nt][2] * d1, c[nt][3] * d1);
    }
}

// ---------------------------------------------------------------------------
extern "C" void kernel_launch(void* const* d_in, const int* in_sizes, int n_in,
                              void* d_out, int out_size) {
    const float* x   = (const float*)d_in[0];
    const int*   ei  = (const int*)d_in[1];   // [2, E] int32
    const float* W1  = (const float*)d_in[2];
    const float* b1  = (const float*)d_in[3];
    const float* W2  = (const float*)d_in[4];
    const float* b2  = (const float*)d_in[5];
    float*       out = (float*)d_out;

    const int* src = ei;
    const int* dst = ei + N_EDGES;

    cudaFuncSetAttribute(k_gemm1, cudaFuncAttributeMaxDynamicSharedMemorySize, G1_SMEM);
    cudaFuncSetAttribute(k_gemm2, cudaFuncAttributeMaxDynamicSharedMemorySize, G2_SMEM);

    // degree zero via memset node
    void* degi_ptr = nullptr;
    cudaGetSymbolAddress(&degi_ptr, g_degi);
    cudaMemsetAsync(degi_ptr, 0, N_NODES * sizeof(int));

    // degree + dinv + CSR (+ fused prescale in scan_chunk)
    k_deg_count<<<(N_EDGES + 255) / 256, 256>>>(dst);
    k_scan_chunk<<<N_CHUNKS, 1024>>>(x);              // dinv + prescale fused
    k_scan_sums<<<1, 128>>>();
    k_row_ptr  <<<(N_NODES + 255) / 256, 256>>>();
    k_csr_fill <<<(N_EDGES + 255) / 256, 256>>>(src, dst);

    // layer 1: pull(64-dim fp16, warp/node) -> tensor gemm(+bias+relu)
    k_pull1<<<(N_NODES * 32 + 255) / 256, 256>>>();
    k_gemm1<<<N_PAD / 64, 256, G1_SMEM>>>(W1, b1);

    // layer 2: tensor gemm(*dinv -> fp16) -> pull(64-dim fp16, +bias)
    k_gemm2<<<N_PAD / 64, 256, G2_SMEM>>>(W2);
    k_pull2<<<(N_NODES * 32 + 255) / 256, 256>>>(b2, out);
}

// round 12
// speedup vs baseline: 1.0679x; 1.0615x over previous
#include <cuda_runtime.h>
#include <cuda_fp16.h>

#define N_NODES 100000
#define N_PAD   100032   // multiple of 64
#define N_EDGES 3200000
#define F0 64
#define F1 128
#define F2 64
#define N_CHUNKS 98   // ceil(100000/1024)

// Scratch (static __device__ arrays)
__device__ int   g_degi[N_NODES];
__device__ int   g_scan[N_NODES];
__device__ int   g_chunksum[N_CHUNKS];
__device__ int   g_row [N_NODES + 1];
__device__ int   g_cur [N_NODES];
__device__ int   g_csr [N_EDGES];
__device__ float g_dinv[N_PAD];
__device__ uint4 g_xh  [N_NODES * 8];   // fp16: x * dinv[node] (8 halves per uint4)
__device__ float g_ag  [N_PAD * F0];    // fp32 aggregated input-space features
__device__ float g_h2  [N_PAD * F1];    // fp32 relu'd layer-1 output
__device__ uint4 g_h2h [N_PAD * 8];     // fp16: (h2 @ W2) * dinv

// ---------------------------------------------------------------------------
__global__ void k_deg_count(const int* __restrict__ dst) {
    int e = (blockIdx.x * blockDim.x + threadIdx.x) * 2;
    if (e < N_EDGES) {
        int2 d = *(const int2*)&dst[e];
        atomicAdd(&g_degi[d.x], 1);
        atomicAdd(&g_degi[d.y], 1);
    }
}

__device__ __forceinline__ unsigned pack2(float lo, float hi) {
    __half2 h = __floats2half2_rn(lo, hi);
    return *(unsigned*)&h;
}

// Scan chunk + dinv + fused prescale of this chunk's x rows (float4 -> uint2).
__global__ void k_scan_chunk(const float* __restrict__ x) {
    __shared__ int sh[1024];
    __shared__ float sdinv[1024];
    int gid = blockIdx.x * 1024 + threadIdx.x;
    int v = (gid < N_NODES) ? g_degi[gid] : 0;
    float di = rsqrtf((float)(v + 1));       // self-loop included
    if (gid < N_PAD) g_dinv[gid] = di;
    sdinv[threadIdx.x] = di;
    sh[threadIdx.x] = v;
    __syncthreads();
    #pragma unroll
    for (int off = 1; off < 1024; off <<= 1) {
        int t = (threadIdx.x >= off) ? sh[threadIdx.x - off] : 0;
        __syncthreads();
        sh[threadIdx.x] += t;
        __syncthreads();
    }
    if (gid < N_NODES) g_scan[gid] = sh[threadIdx.x];     // inclusive
    if (threadIdx.x == 1023) g_chunksum[blockIdx.x] = sh[1023];

    // Fused prescale: 1024 nodes x 16 uint2 (each from one float4 of x).
    uint2* xh2 = (uint2*)g_xh;
    int base2 = blockIdx.x * 1024 * 16;
    for (int t = threadIdx.x; t < 1024 * 16; t += 1024) {
        int idx2 = base2 + t;
        if (idx2 < N_NODES * 16) {
            float dd = sdinv[t >> 4];
            float4 a = *(const float4*)&x[(size_t)idx2 * 4];
            xh2[idx2] = make_uint2(pack2(a.x * dd, a.y * dd), pack2(a.z * dd, a.w * dd));
        }
    }
}

// row_ptr with chunk-offset scan folded in (each block rescans the 98 sums).
__global__ void k_row_ptr() {
    __shared__ int sh[128];
    __shared__ int orig[128];
    int tid = threadIdx.x;   // 256
    if (tid < 128) {
        int v = (tid < N_CHUNKS) ? g_chunksum[tid] : 0;
        sh[tid] = v;
        orig[tid] = v;
    }
    __syncthreads();
    #pragma unroll
    for (int off = 1; off < 128; off <<= 1) {
        int t = 0;
        if (tid < 128 && tid >= off) t = sh[tid - off];
        __syncthreads();
        if (tid < 128) sh[tid] += t;
        __syncthreads();
    }
    int i = blockIdx.x * blockDim.x + tid;
    if (i < N_NODES) {
        int c = i >> 10;
        int excl = sh[c] - orig[c];
        int r = g_scan[i] - g_degi[i] + excl;
        g_row[i] = r;
        g_cur[i] = r;
    }
    if (i == 0) g_row[N_NODES] = N_EDGES;
}

__global__ void k_csr_fill(const int* __restrict__ src, const int* __restrict__ dst) {
    int e = (blockIdx.x * blockDim.x + threadIdx.x) * 2;
    if (e < N_EDGES) {
        int2 s = *(const int2*)&src[e];
        int2 d = *(const int2*)&dst[e];
        int p0 = atomicAdd(&g_cur[d.x], 1);
        g_csr[p0] = s.x;
        int p1 = atomicAdd(&g_cur[d.y], 1);
        g_csr[p1] = s.y;
    }
}

// ---------------------------------------------------------------------------
// Pull (64-dim fp16, fp32 accum): QUARTER-warp (8 lanes) per node, uint4/lane.
// One LDG/SHFL instruction serves 4 edges (one per subgroup). MLP-4 staging.
// ---------------------------------------------------------------------------
__device__ __forceinline__ void acc_u4(float2 acc[4], uint4 u) {
    float2 f;
    f = __half22float2(*(__half2*)&u.x); acc[0].x += f.x; acc[0].y += f.y;
    f = __half22float2(*(__half2*)&u.y); acc[1].x += f.x; acc[1].y += f.y;
    f = __half22float2(*(__half2*)&u.z); acc[2].x += f.x; acc[2].y += f.y;
    f = __half22float2(*(__half2*)&u.w); acc[3].x += f.x; acc[3].y += f.y;
}

__device__ __forceinline__ void pull64q(const uint4* __restrict__ feat,
                                        int node, int sub, unsigned qmask,
                                        float2 acc[4]) {
    int beg = g_row[node], end = g_row[node + 1];
    acc_u4(acc, feat[(size_t)node * 8 + sub]);         // self-loop
    for (int e0 = beg; e0 < end; e0 += 8) {
        int n = end - e0;
        int s = (sub < n) ? g_csr[e0 + sub] : 0;
        int cnt = min(n, 8);
        int i = 0;
        for (; i + 4 <= cnt; i += 4) {
            uint4 u[4];
            #pragma unroll
            for (int j = 0; j < 4; ++j) {
                int ss = __shfl_sync(qmask, s, i + j, 8);
                u[j] = feat[(size_t)ss * 8 + sub];
            }
            #pragma unroll
            for (int j = 0; j < 4; ++j) acc_u4(acc, u[j]);
        }
        for (; i < cnt; ++i) {
            int ss = __shfl_sync(qmask, s, i, 8);
            acc_u4(acc, feat[(size_t)ss * 8 + sub]);
        }
    }
}

__global__ void k_pull1() {
    int lane = threadIdx.x & 31;
    int sub  = lane & 7;
    unsigned qmask = 0xFFu << ((lane >> 3) * 8);
    int node = (blockIdx.x * blockDim.x + threadIdx.x) >> 3;
    if (node >= N_NODES) return;
    float2 acc[4] = { {0,0}, {0,0}, {0,0}, {0,0} };
    pull64q(g_xh, node, sub, qmask, acc);
    float di = g_dinv[node];
    float4 o0 = { acc[0].x * di, acc[0].y * di, acc[1].x * di, acc[1].y * di };
    float4 o1 = { acc[2].x * di, acc[2].y * di, acc[3].x * di, acc[3].y * di };
    *(float4*)&g_ag[(size_t)node * F0 + sub * 8]     = o0;
    *(float4*)&g_ag[(size_t)node * F0 + sub * 8 + 4] = o1;
}

__global__ void k_pull2(const float* __restrict__ b2, float* __restrict__ out) {
    int lane = threadIdx.x & 31;
    int sub  = lane & 7;
    unsigned qmask = 0xFFu << ((lane >> 3) * 8);
    int node = (blockIdx.x * blockDim.x + threadIdx.x) >> 3;
    if (node >= N_NODES) return;
    float2 acc[4] = { {0,0}, {0,0}, {0,0}, {0,0} };
    pull64q(g_h2h, node, sub, qmask, acc);
    float di = g_dinv[node];
    float4 b0 = *(const float4*)&b2[sub * 8];
    float4 b1 = *(const float4*)&b2[sub * 8 + 4];
    float4 o0 = { fmaf(acc[0].x, di, b0.x), fmaf(acc[0].y, di, b0.y),
                  fmaf(acc[1].x, di, b0.z), fmaf(acc[1].y, di, b0.w) };
    float4 o1 = { fmaf(acc[2].x, di, b1.x), fmaf(acc[2].y, di, b1.y),
                  fmaf(acc[3].x, di, b1.z), fmaf(acc[3].y, di, b1.w) };
    *(float4*)&out[(size_t)node * F2 + sub * 8]     = o0;
    *(float4*)&out[(size_t)node * F2 + sub * 8 + 4] = o1;
}

// ---------------------------------------------------------------------------
// tf32 helpers
// ---------------------------------------------------------------------------
__device__ __forceinline__ float tf32r(float f) {
    unsigned u;
    asm("cvt.rna.tf32.f32 %0, %1;" : "=r"(u) : "f"(f));
    return __uint_as_float(u);
}

__device__ __forceinline__ void mma_tf32(float c[4], unsigned a0, unsigned a1,
                                         unsigned a2, unsigned a3,
                                         unsigned b0, unsigned b1) {
    asm volatile(
        "mma.sync.aligned.m16n8k8.row.col.f32.tf32.tf32.f32 "
        "{%0,%1,%2,%3}, {%4,%5,%6,%7}, {%8,%9}, {%0,%1,%2,%3};"
        : "+f"(c[0]), "+f"(c[1]), "+f"(c[2]), "+f"(c[3])
        : "r"(a0), "r"(a1), "r"(a2), "r"(a3), "r"(b0), "r"(b1));
}

// ---------------------------------------------------------------------------
// GEMM1 (tensor): h2 = relu(ag @ W1 + b1).  Tile 64x128, K=64, 256 threads.
// ---------------------------------------------------------------------------
#define G1_SMEM ((128 * 68 + 64 * 68) * 4)
__global__ void k_gemm1(const float* __restrict__ W1, const float* __restrict__ b1) {
    extern __shared__ float sm[];
    float* Wt = sm;              // [128][68]
    float* As = sm + 128 * 68;   // [64][68]
    int tid = threadIdx.x;       // 256

    for (int i = tid; i < F0 * F1; i += 256) {
        int k = i >> 7, n = i & 127;
        Wt[n * 68 + k] = tf32r(W1[i]);
    }
    int r0 = blockIdx.x * 64;
    #pragma unroll
    for (int t = 0; t < 4; ++t) {
        int f4 = tid + t * 256;
        int r = f4 >> 4, c = (f4 & 15) * 4;
        float4 v = *(const float4*)&g_ag[(size_t)(r0 + r) * F0 + c];
        As[r * 68 + c + 0] = tf32r(v.x);
        As[r * 68 + c + 1] = tf32r(v.y);
        As[r * 68 + c + 2] = tf32r(v.z);
        As[r * 68 + c + 3] = tf32r(v.w);
    }
    __syncthreads();

    int lane = tid & 31, warp = tid >> 5;
    int wr = (warp & 3) * 16;
    int wc = (warp >> 2) * 64;
    int g = lane >> 2, tg = lane & 3;

    float c[8][4];
    #pragma unroll
    for (int nt = 0; nt < 8; ++nt)
        c[nt][0] = c[nt][1] = c[nt][2] = c[nt][3] = 0.f;

    #pragma unroll
    for (int ks = 0; ks < 8; ++ks) {
        int k0 = ks * 8 + tg;
        unsigned a0 = __float_as_uint(As[(wr + g    ) * 68 + k0]);
        unsigned a1 = __float_as_uint(As[(wr + g + 8) * 68 + k0]);
        unsigned a2 = __float_as_uint(As[(wr + g    ) * 68 + k0 + 4]);
        unsigned a3 = __float_as_uint(As[(wr + g + 8) * 68 + k0 + 4]);
        #pragma unroll
        for (int nt = 0; nt < 8; ++nt) {
            const float* bp = &Wt[(wc + nt * 8 + g) * 68 + k0];
            mma_tf32(c[nt], a0, a1, a2, a3,
                     __float_as_uint(bp[0]), __float_as_uint(bp[4]));
        }
    }

    #pragma unroll
    for (int nt = 0; nt < 8; ++nt) {
        int col = wc + nt * 8 + tg * 2;
        float2 bb = *(const float2*)&b1[col];
        int row = r0 + wr + g;
        float2 o0 = { fmaxf(c[nt][0] + bb.x, 0.f), fmaxf(c[nt][1] + bb.y, 0.f) };
        *(float2*)&g_h2[(size_t)row * F1 + col] = o0;
        float2 o1 = { fmaxf(c[nt][2] + bb.x, 0.f), fmaxf(c[nt][3] + bb.y, 0.f) };
        *(float2*)&g_h2[(size_t)(row + 8) * F1 + col] = o1;
    }
}

// ---------------------------------------------------------------------------
// GEMM2 (tensor): h2h = half((h2 @ W2) * dinv).  Tile 64x64, K=128.
// ---------------------------------------------------------------------------
#define G2_SMEM ((64 * 132 + 64 * 132) * 4)
__global__ void k_gemm2(const float* __restrict__ W2) {
    extern __shared__ float sm[];
    float* Wt = sm;              // [64][132]
    float* As = sm + 64 * 132;   // [64][132]
    int tid = threadIdx.x;       // 256

    for (int i = tid; i < F1 * F2; i += 256) {
        int k = i >> 6, n = i & 63;
        Wt[n * 132 + k] = tf32r(W2[i]);
    }
    int r0 = blockIdx.x * 64;
    #pragma unroll
    for (int t = 0; t < 8; ++t) {
        int f4 = tid + t * 256;
        int r = f4 >> 5, c = (f4 & 31) * 4;
        float4 v = *(const float4*)&g_h2[(size_t)(r0 + r) * F1 + c];
        As[r * 132 + c + 0] = tf32r(v.x);
        As[r * 132 + c + 1] = tf32r(v.y);
        As[r * 132 + c + 2] = tf32r(v.z);
        As[r * 132 + c + 3] = tf32r(v.w);
    }
    __syncthreads();

    int lane = tid & 31, warp = tid >> 5;
    int wr = (warp & 3) * 16;
    int wc = (warp >> 2) * 32;
    int g = lane >> 2, tg = lane & 3;

    float c[4][4];
    #pragma unroll
    for (int nt = 0; nt < 4; ++nt)
        c[nt][0] = c[nt][1] = c[nt][2] = c[nt][3] = 0.f;

    #pragma unroll
    for (int ks = 0; ks < 16; ++ks) {
        int k0 = ks * 8 + tg;
        unsigned a0 = __float_as_uint(As[(wr + g    ) * 132 + k0]);
        unsigned a1 = __float_as_uint(As[(wr + g + 8) * 132 + k0]);
        unsigned a2 = __float_as_uint(As[(wr + g    ) * 132 + k0 + 4]);
        unsigned a3 = __float_as_uint(As[(wr + g + 8) * 132 + k0 + 4]);
        #pragma unroll
        for (int nt = 0; nt < 4; ++nt) {
            const float* bp = &Wt[(wc + nt * 8 + g) * 132 + k0];
            mma_tf32(c[nt], a0, a1, a2, a3,
                     __float_as_uint(bp[0]), __float_as_uint(bp[4]));
        }
    }

    unsigned* h2u = (unsigned*)g_h2h;   // 32 unsigneds per row
    #pragma unroll
    for (int nt = 0; nt < 4; ++nt) {
        int col = wc + nt * 8 + tg * 2;
        int row = r0 + wr + g;
        float d0 = g_dinv[row];
        h2u[(size_t)row * 32 + (col >> 1)] = pack2(c[nt][0] * d0, c[nt][1] * d0);
        float d1 = g_dinv[row + 8];
        h2u[(size_t)(row + 8) * 32 + (col >> 1)] = pack2(c[nt][2] * d1, c[nt][3] * d1);
    }
}

// ---------------------------------------------------------------------------
extern "C" void kernel_launch(void* const* d_in, const int* in_sizes, int n_in,
                              void* d_out, int out_size) {
    const float* x   = (const float*)d_in[0];
    const int*   ei  = (const int*)d_in[1];   // [2, E] int32
    const float* W1  = (const float*)d_in[2];
    const float* b1  = (const float*)d_in[3];
    const float* W2  = (const float*)d_in[4];
    const float* b2  = (const float*)d_in[5];
    float*       out = (float*)d_out;

    const int* src = ei;
    const int* dst = ei + N_EDGES;

    cudaFuncSetAttribute(k_gemm1, cudaFuncAttributeMaxDynamicSharedMemorySize, G1_SMEM);
    cudaFuncSetAttribute(k_gemm2, cudaFuncAttributeMaxDynamicSharedMemorySize, G2_SMEM);

    // degree zero via memset node
    void* degi_ptr = nullptr;
    cudaGetSymbolAddress(&degi_ptr, g_degi);
    cudaMemsetAsync(degi_ptr, 0, N_NODES * sizeof(int));

    // degree + dinv + CSR (+ fused prescale; scan_sums folded into row_ptr)
    k_deg_count<<<(N_EDGES / 2 + 255) / 256, 256>>>(dst);
    k_scan_chunk<<<N_CHUNKS, 1024>>>(x);
    k_row_ptr  <<<(N_NODES + 255) / 256, 256>>>();
    k_csr_fill <<<(N_EDGES / 2 + 255) / 256, 256>>>(src, dst);

    // layer 1: pull(quarter-warp) -> tensor gemm(+bias+relu)
    k_pull1<<<(N_NODES * 8 + 255) / 256, 256>>>();
    k_gemm1<<<N_PAD / 64, 256, G1_SMEM>>>(W1, b1);

    // layer 2: tensor gemm(*dinv -> fp16) -> pull(quarter-warp, +bias)
    k_gemm2<<<N_PAD / 64, 256, G2_SMEM>>>(W2);
    k_pull2<<<(N_NODES * 8 + 255) / 256, 256>>>(b2, out);
}